// round 16
// baseline (speedup 1.0000x reference)
#include <cuda_runtime.h>
#include <math.h>

#define NU 50000
#define NI 100000
#define NE 200000
#define NREL 32
#define DIM 64
#define NB 4096
#define EKG 2000000
#define EUI_HALF 1000000
#define NNODES 150000      // NU + NI

#define MAXLE NI           // upper bound on live entities
#define MAXLN (3 * NB)     // upper bound on live node rows = 12288

#define GEMM_BLOCKS ((NE + 255) / 256)          // 782
#define ZF4_AGGC  (MAXLE * DIM / 4)             // 1,600,000
#define CZBLOCKS  ((ZF4_AGGC + 2047) / 2048)    // 782
#define GZ_BLOCKS (GEMM_BLOCKS + CZBLOCKS)

#define KGC8_BLOCKS ((EKG / 8 + 255) / 256)     // 977
#define CUI4_BLOCKS ((EUI_HALF / 4 + 255) / 256) // 977
#define SF2_QBLOCKS ((2 * NB + 255) / 256)      // 32
#define SF2_BLOCKS (2 * CUI4_BLOCKS + SF2_QBLOCKS)

#define EKG_BLOCKS 2048
#define EUI_BLOCKS 256
#define EB_BLOCKS 512

#define DEGZ_F4 (MAXLE / 4)                     // 25,000
#define ZA2_F4 (MAXLN * DIM / 4)                // 196,608 float4
#define ZA2_T (ZA2_F4 / 8)                      // 24,576 threads x 8 f4
#define SF1_THREADS (3 * NB + DEGZ_F4 + ZA2_T)  // 61,864
#define SF1_BLOCKS ((SF1_THREADS + 255) / 256)

#define QK_BLOCKS 512                           // NB*32/256

// ---------------- scratch (static device globals; no allocation) ----------------
__device__ float g_y[NE * DIM];             // entity_emb @ W^T
__device__ float g_aggC[MAXLE * DIM];       // KG segment sum (dense live-entity rows)
__device__ float g_degC[MAXLE];             // KG in-degree (dense; zeroed each call)
__device__ float g_itemkg[NI * DIM];        // per-item post-processed KG embedding
__device__ float g_agg2C[MAXLN * DIM];      // UI segment sum (dense live-node rows)
__device__ float g_gate[NREL * DIM];        // sigmoid(relation_emb)
__device__ int g_remapE[NE];                // 0=unclaimed, >=2 -> dense id+2 (PERSISTENT,
__device__ int g_remapN[NNODES];            //   input-deterministic, idempotent claims)
__device__ int g_nLiveE, g_nLiveN;
__device__ int g_nKG, g_nUIA, g_nUIB;       // compaction counters (reset in SF1 t==0)
__device__ int   g_ksr[EKG];                // src | rel<<18
__device__ int   g_kdst[EKG];               // remapped dense dst
__device__ int   g_apk[EUI_HALF];           // rr | cc<<14 (A: row=item live id, col=user)
__device__ float g_aval[EUI_HALF];
__device__ int   g_bpk[EUI_HALF];           // rr | cc<<14 (B: row=user live id, col=item node)
__device__ float g_bval[EUI_HALF];

// vectorized no-return global atomic add (sm_90+)
__device__ __forceinline__ void red_add_v4(float* addr, float x, float y, float z, float w) {
    asm volatile("red.global.add.v4.f32 [%0], {%1,%2,%3,%4};"
                 :: "l"(addr), "f"(x), "f"(y), "f"(z), "f"(w)
                 : "memory");
}

__device__ __forceinline__ unsigned long long pack2(float a, float b) {
    unsigned long long r;
    asm("mov.b64 %0, {%1, %2};" : "=l"(r) : "f"(a), "f"(b));
    return r;
}
__device__ __forceinline__ void unpack2(unsigned long long v, float& a, float& b) {
    asm("mov.b64 {%0, %1}, %2;" : "=f"(a), "=f"(b) : "l"(v));
}
__device__ __forceinline__ void fma2(unsigned long long& d, unsigned long long a,
                                     unsigned long long b) {
    asm("fma.rn.f32x2 %0, %1, %2, %3;" : "=l"(d) : "l"(a), "l"(b), "l"(d));
}

__device__ __forceinline__ void claimE(int ent) {
    if (atomicCAS(&g_remapE[ent], 0, 1) == 0)
        g_remapE[ent] = 2 + atomicAdd(&g_nLiveE, 1);
}

// warp-scan compaction helper: cnt in [0,8]; returns write base for this thread
__device__ __forceinline__ int warp_scan_base(int cnt, int lane, int* counter) {
    int inc = cnt;
#pragma unroll
    for (int o = 1; o < 32; o <<= 1) {
        int v = __shfl_up_sync(0xffffffffu, inc, o);
        if (lane >= o) inc += v;
    }
    int total = __shfl_sync(0xffffffffu, inc, 31);
    int base = 0;
    if (lane == 0 && total) base = atomicAdd(counter, total);
    base = __shfl_sync(0xffffffffu, base, 0);
    return base + inc - cnt;
}

// ---------------- SIDE STREAM: GEMM + gate + zero aggC (no deps) ----------------
__global__ void gemm_zero_kernel(const float* __restrict__ x, const float* __restrict__ W,
                                 const float* __restrict__ rel_emb) {
    int b = blockIdx.x;
    int tid = threadIdx.x;  // 256
    if (b < GEMM_BLOCKS) {
        __shared__ float sWt[DIM][DIM];   // sWt[k][o] = W[o][k]
        for (int idx = tid; idx < DIM * DIM; idx += 256) {
            int o = idx >> 6, k = idx & 63;
            sWt[k][o] = W[idx];
        }
        __syncthreads();
        int row = b * 256 + tid;
        if (row >= NE) return;
        const float4* xp = reinterpret_cast<const float4*>(x + (size_t)row * DIM);
        unsigned long long acc[32];
#pragma unroll
        for (int m = 0; m < 32; m++) acc[m] = 0ull;
#pragma unroll 4
        for (int kc = 0; kc < 16; kc++) {
            float4 xq = __ldg(xp + kc);
#pragma unroll
            for (int j = 0; j < 4; j++) {
                float xv = (j == 0) ? xq.x : (j == 1) ? xq.y : (j == 2) ? xq.z : xq.w;
                unsigned long long xx = pack2(xv, xv);
                const float4* wrow = reinterpret_cast<const float4*>(sWt[kc * 4 + j]);
#pragma unroll
                for (int o4 = 0; o4 < 16; o4++) {
                    float4 w = wrow[o4];
                    fma2(acc[2 * o4],     xx, pack2(w.x, w.y));
                    fma2(acc[2 * o4 + 1], xx, pack2(w.z, w.w));
                }
            }
        }
        float4* yp = reinterpret_cast<float4*>(g_y + (size_t)row * DIM);
#pragma unroll
        for (int j = 0; j < 16; j++) {
            float a0, a1, b0, b1;
            unpack2(acc[2 * j], a0, a1);
            unpack2(acc[2 * j + 1], b0, b1);
            yp[j] = make_float4(a0, a1, b0, b1);
        }
        return;
    }
    b -= GEMM_BLOCKS;
    {
        if (b == 0) {
            for (int i = tid; i < NREL * DIM; i += 256) {
                float v = rel_emb[i];
                g_gate[i] = 1.0f / (1.0f + __expf(-v));
            }
        }
        float4 z = make_float4(0.f, 0.f, 0.f, 0.f);
        int base = b * 2048 + tid;
#pragma unroll
        for (int j = 0; j < 8; j++) {
            int i = base + j * 256;
            if (i < ZF4_AGGC) reinterpret_cast<float4*>(g_aggC)[i] = z;
        }
    }
}

// ---------------- K1 (SF1): batch-node tickets + zero degC + zero agg2C + reset counters ----------------
__global__ void sf1_kernel(const int* __restrict__ qu,
                           const int* __restrict__ qi,
                           const int* __restrict__ qn) {
    int t = blockIdx.x * blockDim.x + threadIdx.x;
    if (t == 0) { g_nKG = 0; g_nUIA = 0; g_nUIB = 0; }
    if (t < 3 * NB) {
        int node;
        if (t < NB) node = __ldg(qu + t);
        else if (t < 2 * NB) node = NU + __ldg(qi + t - NB);
        else node = NU + __ldg(qn + t - 2 * NB);
        if (atomicCAS(&g_remapN[node], 0, 1) == 0)
            g_remapN[node] = 2 + atomicAdd(&g_nLiveN, 1);
    } else if (t < 3 * NB + DEGZ_F4) {
        int z = t - 3 * NB;
        reinterpret_cast<float4*>(g_degC)[z] = make_float4(0.f, 0.f, 0.f, 0.f);
    } else if (t < SF1_THREADS) {
        int z = (t - 3 * NB - DEGZ_F4) * 8;
        float4 zf = make_float4(0.f, 0.f, 0.f, 0.f);
#pragma unroll
        for (int j = 0; j < 8; j++)
            reinterpret_cast<float4*>(g_agg2C)[z + j] = zf;
    }
}

// ---------------- K2 (SF2): fused entity claims + UI compaction, 4 edges/thread ----------------
__global__ void sf2_kernel(const int* __restrict__ urow, const int* __restrict__ ucol,
                           const float* __restrict__ uval,
                           const int* __restrict__ i2e,
                           const int* __restrict__ qi, const int* __restrict__ qn) {
    int b = blockIdx.x;
    int tid = threadIdx.x;
    int lane = tid & 31;
    if (b < 2 * CUI4_BLOCKS) {
        int half = (b < CUI4_BLOCKS) ? 0 : 1;
        int bb = (half == 0) ? b : b - CUI4_BLOCKS;
        int t = bb * 256 + tid;          // group index within half
        int cnt = 0;
        int pk[4];
        float vv[4];
        if (t < EUI_HALF / 4) {
            int g = half * (EUI_HALF / 4) + t;  // global int4 index
            int4 r4 = __ldg(reinterpret_cast<const int4*>(urow) + g);
            int4 c4 = __ldg(reinterpret_cast<const int4*>(ucol) + g);
            float4 v4 = __ldg(reinterpret_cast<const float4*>(uval) + g);
            int rows[4] = {r4.x, r4.y, r4.z, r4.w};
            int cols[4] = {c4.x, c4.y, c4.z, c4.w};
            float vals[4] = {v4.x, v4.y, v4.z, v4.w};
            int m0 = g_remapN[rows[0]];
            int m1 = g_remapN[rows[1]];
            int m2 = g_remapN[rows[2]];
            int m3 = g_remapN[rows[3]];
            int ms[4] = {m0, m1, m2, m3};
#pragma unroll
            for (int i = 0; i < 4; i++) {
                if (ms[i] >= 2) {
                    pk[cnt] = (ms[i] - 2) | (cols[i] << 14);
                    vv[cnt] = vals[i];
                    cnt++;
                    if (half == 0) claimE(__ldg(i2e + (cols[i] - NU)));
                }
            }
        }
        int off = warp_scan_base(cnt, lane, half ? &g_nUIA : &g_nUIB);
        if (half) {
            for (int i = 0; i < cnt; i++) { g_apk[off + i] = pk[i]; g_aval[off + i] = vv[i]; }
        } else {
            for (int i = 0; i < cnt; i++) { g_bpk[off + i] = pk[i]; g_bval[off + i] = vv[i]; }
        }
    } else {
        int r = (b - 2 * CUI4_BLOCKS) * 256 + tid;
        if (r < NB) claimE(__ldg(i2e + __ldg(qi + r)));
        else if (r < 2 * NB) claimE(__ldg(i2e + __ldg(qn + r - NB)));
    }
}

// ---------------- K3: UI user-gather edges (A list): main chain, overlaps GEMM ----------------
__global__ void edge_ui_kernel(const float* __restrict__ user_emb) {
    int tid = threadIdx.x;
    int q = tid & 7;
    int n = g_nUIA;
    int slot = (blockIdx.x * 256 + tid) >> 3;
    for (; slot < n; slot += (EUI_BLOCKS * 256) / 8) {
        int pk = g_apk[slot];
        int rr = pk & 0x3FFF, cc = (int)((unsigned)pk >> 14);
        float w = g_aval[slot];
        const float4* sp = reinterpret_cast<const float4*>(user_emb + (size_t)cc * DIM) + q;
        float4 v0 = __ldg(sp);
        float4 v1 = __ldg(sp + 8);
        float* ap = g_agg2C + (size_t)rr * DIM + q * 4;
        red_add_v4(ap,      w * v0.x, w * v0.y, w * v0.z, w * v0.w);
        red_add_v4(ap + 32, w * v1.x, w * v1.y, w * v1.z, w * v1.w);
    }
}

// ---------------- K4: KG edge compaction + deg, 8 edges/thread ----------------
__global__ void kg_compact_kernel(const int* __restrict__ ksrc, const int* __restrict__ kdst,
                                  const int* __restrict__ krel) {
    int tid = threadIdx.x;
    int lane = tid & 31;
    int t = blockIdx.x * 256 + tid;      // 8-edge group index
    int cnt = 0;
    int srO[8], drO[8];
    if (t < EKG / 8) {
        int4 d4a = __ldg(reinterpret_cast<const int4*>(kdst) + 2 * t);
        int4 d4b = __ldg(reinterpret_cast<const int4*>(kdst) + 2 * t + 1);
        int ds[8] = {d4a.x, d4a.y, d4a.z, d4a.w, d4b.x, d4b.y, d4b.z, d4b.w};
        int ms[8];
#pragma unroll
        for (int i = 0; i < 8; i++) ms[i] = g_remapE[ds[i]];
        bool any = false;
#pragma unroll
        for (int i = 0; i < 8; i++) any |= (ms[i] >= 2);
        if (any) {
            int4 s4a = __ldg(reinterpret_cast<const int4*>(ksrc) + 2 * t);
            int4 s4b = __ldg(reinterpret_cast<const int4*>(ksrc) + 2 * t + 1);
            int4 r4a = __ldg(reinterpret_cast<const int4*>(krel) + 2 * t);
            int4 r4b = __ldg(reinterpret_cast<const int4*>(krel) + 2 * t + 1);
            int ss[8] = {s4a.x, s4a.y, s4a.z, s4a.w, s4b.x, s4b.y, s4b.z, s4b.w};
            int rs[8] = {r4a.x, r4a.y, r4a.z, r4a.w, r4b.x, r4b.y, r4b.z, r4b.w};
#pragma unroll
            for (int i = 0; i < 8; i++) {
                if (ms[i] >= 2) {
                    int dr = ms[i] - 2;
                    srO[cnt] = ss[i] | (rs[i] << 18);
                    drO[cnt] = dr;
                    cnt++;
                    atomicAdd(&g_degC[dr], 1.0f);
                }
            }
        }
    }
    int off = warp_scan_base(cnt, lane, &g_nKG);
    for (int i = 0; i < cnt; i++) { g_ksr[off + i] = srO[i]; g_kdst[off + i] = drO[i]; }
}

// ---------------- K5: compacted KG edges (8 thr/edge), post-join ----------------
__global__ void edge_kg_kernel() {
    int tid = threadIdx.x;
    int q = tid & 7;
    int n = g_nKG;
    int slot = (blockIdx.x * 256 + tid) >> 3;
    for (; slot < n; slot += (EKG_BLOCKS * 256) / 8) {
        int sr = g_ksr[slot], dr = g_kdst[slot];
        int s = sr & 0x3FFFF, r = (int)((unsigned)sr >> 18);
        const float4* yp = reinterpret_cast<const float4*>(g_y + (size_t)s * DIM) + q;
        const float4* gp = reinterpret_cast<const float4*>(g_gate + r * DIM) + q;
        float4 v0 = __ldg(yp);
        float4 v1 = __ldg(yp + 8);
        float4 g0 = __ldg(gp);
        float4 g1 = __ldg(gp + 8);
        float* ap = g_aggC + (size_t)dr * DIM + q * 4;
        red_add_v4(ap,      v0.x * g0.x, v0.y * g0.y, v0.z * g0.z, v0.w * g0.w);
        red_add_v4(ap + 32, v1.x * g1.x, v1.y * g1.y, v1.z * g1.z, v1.w * g1.w);
    }
}

// ---------------- K6: per-ITEM post (16 lanes/row, float4), live-entity only ----------------
__global__ void item_post_kernel(const float* __restrict__ ent, const int* __restrict__ i2e) {
    int tid = threadIdx.x;
    int lane = tid & 31;
    int half = lane >> 4;
    int l16 = lane & 15;
    int item = blockIdx.x * 16 + (tid >> 5) * 2 + half;
    if (item >= NI) return;
    int e = __ldg(i2e + item);
    int m = g_remapE[e];
    if (m < 2) return;                 // item not visible to this batch; itemkg never read
    int re = m - 2;
    float inv = 1.0f / fmaxf(g_degC[re], 1.0f);
    float4 a = *reinterpret_cast<const float4*>(&g_aggC[(size_t)re * DIM + l16 * 4]);
    float4 x0 = __ldg(reinterpret_cast<const float4*>(&ent[(size_t)e * DIM + l16 * 4]));
    float vx = fmaf(a.x, inv, x0.x);
    float vy = fmaf(a.y, inv, x0.y);
    float vz = fmaf(a.z, inv, x0.z);
    float vw = fmaf(a.w, inv, x0.w);
    vx = (vx > 0.f) ? vx : (__expf(vx) - 1.f);
    vy = (vy > 0.f) ? vy : (__expf(vy) - 1.f);
    vz = (vz > 0.f) ? vz : (__expf(vz) - 1.f);
    vw = (vw > 0.f) ? vw : (__expf(vw) - 1.f);
    float ss = vx * vx + vy * vy + vz * vz + vw * vw;
#pragma unroll
    for (int o = 8; o; o >>= 1) ss += __shfl_xor_sync(0xffffffffu, ss, o);
    float scale = 1.0f / fmaxf(sqrtf(ss), 1e-12f);
    float4 out = make_float4(vx * scale, vy * scale, vz * scale, vw * scale);
    *reinterpret_cast<float4*>(&g_itemkg[(size_t)item * DIM + l16 * 4]) = out;
}

// ---------------- K7: compacted UI item-gather edges (8 thr/edge) ----------------
__global__ void edgeB_kernel() {
    int tid = threadIdx.x;
    int q = tid & 7;
    int n = g_nUIB;
    int slot = (blockIdx.x * 256 + tid) >> 3;
    for (; slot < n; slot += (EB_BLOCKS * 256) / 8) {
        int pk = g_bpk[slot];
        int rr = pk & 0x3FFF, cc = (int)((unsigned)pk >> 14);
        float w = g_bval[slot];
        const float4* sp = reinterpret_cast<const float4*>(g_itemkg + (size_t)(cc - NU) * DIM) + q;
        float4 v0 = __ldg(sp);
        float4 v1 = __ldg(sp + 8);
        float* ap = g_agg2C + (size_t)rr * DIM + q * 4;
        red_add_v4(ap,      w * v0.x, w * v0.y, w * v0.z, w * v0.w);
        red_add_v4(ap + 32, w * v1.x, w * v1.y, w * v1.z, w * v1.w);
    }
}

// ---------------- K8: fused intent + queries ----------------
__global__ void query_kernel(const int* __restrict__ qu, const int* __restrict__ qi,
                             const int* __restrict__ qn,
                             const float* __restrict__ user_emb,
                             const float* __restrict__ router_w,
                             const float* __restrict__ router_b,
                             const float* __restrict__ iw,
                             const float* __restrict__ rel_emb,
                             float* __restrict__ out) {
    __shared__ float s_intent[2 * DIM];
    __shared__ float s_sw[2][NREL];
    int tid = threadIdx.x;  // 256
    if (tid < 2) {
        float m = -1e30f;
#pragma unroll
        for (int k = 0; k < NREL; k++) m = fmaxf(m, __ldg(iw + tid * NREL + k));
        float s = 0.f;
#pragma unroll
        for (int k = 0; k < NREL; k++) {
            float e = __expf(__ldg(iw + tid * NREL + k) - m);
            s_sw[tid][k] = e; s += e;
        }
        float inv = 1.0f / s;
#pragma unroll
        for (int k = 0; k < NREL; k++) s_sw[tid][k] *= inv;
    }
    __syncthreads();
    if (tid < 64) {
#pragma unroll
        for (int intent = 0; intent < 2; intent++) {
            float acc = 0.f;
#pragma unroll
            for (int k = 0; k < NREL; k++) acc += s_sw[intent][k] * __ldg(rel_emb + k * DIM + tid);
            s_intent[intent * DIM + tid] = acc;
        }
    }
    __syncthreads();

    int warp = (blockIdx.x * blockDim.x + tid) >> 5;
    int lane = tid & 31;
    if (warp >= NB) return;
    int uu = __ldg(qu + warp), pi = __ldg(qi + warp), ni = __ldg(qn + warp);
    int ru = g_remapN[uu] - 2;
    int rp = g_remapN[NU + pi] - 2;
    int rn = g_remapN[NU + ni] - 2;

    float2 ue0 = __ldg(reinterpret_cast<const float2*>(&user_emb[(size_t)uu * DIM + lane * 2]));
    float2 ag = *reinterpret_cast<const float2*>(&g_agg2C[(size_t)ru * DIM + lane * 2]);
    float fux = 0.5f * (ue0.x + ag.x);
    float fuy = 0.5f * (ue0.y + ag.y);

    float2 rw0 = __ldg(reinterpret_cast<const float2*>(&router_w[lane * 2]));
    float2 rw1 = __ldg(reinterpret_cast<const float2*>(&router_w[DIM + lane * 2]));
    float l0 = fux * rw0.x + fuy * rw0.y;
    float l1 = fux * rw1.x + fuy * rw1.y;
#pragma unroll
    for (int o = 16; o; o >>= 1) {
        l0 += __shfl_xor_sync(0xffffffffu, l0, o);
        l1 += __shfl_xor_sync(0xffffffffu, l1, o);
    }
    l0 += __ldg(router_b + 0);
    l1 += __ldg(router_b + 1);
    float m = fmaxf(l0, l1);
    float e0 = __expf(l0 - m), e1 = __expf(l1 - m);
    float inv = 1.0f / (e0 + e1);
    float p0 = e0 * inv, p1 = e1 * inv;

    float2 i0 = *reinterpret_cast<const float2*>(&s_intent[lane * 2]);
    float2 i1 = *reinterpret_cast<const float2*>(&s_intent[DIM + lane * 2]);
    float uex = fux + p0 * i0.x + p1 * i1.x;
    float uey = fuy + p0 * i0.y + p1 * i1.y;

    float2 ik = *reinterpret_cast<const float2*>(&g_itemkg[(size_t)pi * DIM + lane * 2]);
    float2 a2 = *reinterpret_cast<const float2*>(&g_agg2C[(size_t)rp * DIM + lane * 2]);
    float pos = uex * (1.5f * ik.x + 0.5f * a2.x) + uey * (1.5f * ik.y + 0.5f * a2.y);

    float2 nk = *reinterpret_cast<const float2*>(&g_itemkg[(size_t)ni * DIM + lane * 2]);
    float2 n2 = *reinterpret_cast<const float2*>(&g_agg2C[(size_t)rn * DIM + lane * 2]);
    float neg = uex * (1.5f * nk.x + 0.5f * n2.x) + uey * (1.5f * nk.y + 0.5f * n2.y);

#pragma unroll
    for (int o = 16; o; o >>= 1) {
        pos += __shfl_xor_sync(0xffffffffu, pos, o);
        neg += __shfl_xor_sync(0xffffffffu, neg, o);
    }
    if (lane == 0) {
        out[warp] = pos;
        out[NB + warp] = neg;
    }
}

// ---------------- launch (fork/join) ----------------
extern "C" void kernel_launch(void* const* d_in, const int* in_sizes, int n_in,
                              void* d_out, int out_size) {
    const int*   u          = (const int*)d_in[0];
    const int*   it         = (const int*)d_in[1];
    const int*   neg_i      = (const int*)d_in[2];
    const float* user_emb   = (const float*)d_in[3];
    const float* entity_emb = (const float*)d_in[4];
    const float* rel_emb    = (const float*)d_in[5];
    const float* intent_w   = (const float*)d_in[6];
    const float* router_w   = (const float*)d_in[7];
    const float* router_b   = (const float*)d_in[8];
    const float* kg_w       = (const float*)d_in[9];
    const float* ui_vals    = (const float*)d_in[10];
    const int*   item2ent   = (const int*)d_in[11];
    const int*   kg_src     = (const int*)d_in[12];
    const int*   kg_dst     = (const int*)d_in[13];
    const int*   kg_rel     = (const int*)d_in[14];
    const int*   ui_row     = (const int*)d_in[15];
    const int*   ui_col     = (const int*)d_in[16];
    float* out = (float*)d_out;

    // lazily-created host-side stream/events (no device memory; identical GPU work per call)
    static cudaStream_t s1 = nullptr;
    static cudaEvent_t evFork = nullptr, evJoin = nullptr;
    if (s1 == nullptr) {
        cudaStreamCreateWithFlags(&s1, cudaStreamNonBlocking);
        cudaEventCreateWithFlags(&evFork, cudaEventDisableTiming);
        cudaEventCreateWithFlags(&evJoin, cudaEventDisableTiming);
    }

    // fork: side stream runs GEMM + gate + aggC zeroing (no dependencies)
    cudaEventRecord(evFork, 0);
    cudaStreamWaitEvent(s1, evFork, 0);
    gemm_zero_kernel<<<GZ_BLOCKS, 256, 0, s1>>>(entity_emb, kg_w, rel_emb);
    cudaEventRecord(evJoin, s1);

    // main chain: liveness + compaction + UI user-gather (all independent of g_y/aggC)
    sf1_kernel<<<SF1_BLOCKS, 256>>>(u, it, neg_i);
    sf2_kernel<<<SF2_BLOCKS, 256>>>(ui_row, ui_col, ui_vals, item2ent, it, neg_i);
    kg_compact_kernel<<<KGC8_BLOCKS, 256>>>(kg_src, kg_dst, kg_rel);
    edge_ui_kernel<<<EUI_BLOCKS, 256>>>(user_emb);

    // join: edge_kg needs g_y/gate/aggC-zero from side stream
    cudaStreamWaitEvent(0, evJoin, 0);
    edge_kg_kernel<<<EKG_BLOCKS, 256>>>();
    item_post_kernel<<<(NI + 15) / 16, 256>>>(entity_emb, item2ent);
    edgeB_kernel<<<EB_BLOCKS, 256>>>();
    query_kernel<<<QK_BLOCKS, 256>>>(u, it, neg_i, user_emb, router_w, router_b,
                                     intent_w, rel_emb, out);
}

// round 17
// speedup vs baseline: 1.0341x; 1.0341x over previous
#include <cuda_runtime.h>
#include <math.h>

#define NU 50000
#define NI 100000
#define NE 200000
#define NREL 32
#define DIM 64
#define NB 4096
#define EKG 2000000
#define EUI_HALF 1000000
#define NNODES 150000      // NU + NI

#define MAXLE NI           // upper bound on live entities
#define MAXLN (3 * NB)     // upper bound on live node rows = 12288

#define GEMM_BLOCKS ((NE + 255) / 256)          // 782
#define ZF4_AGGC  (MAXLE * DIM / 4)             // 1,600,000
#define ZF4_AGG2C (MAXLN * DIM / 4)             // 196,608
#define ZF4_TOTC  (ZF4_AGGC + ZF4_AGG2C)
#define CZBLOCKS  ((ZF4_TOTC + 2047) / 2048)    // 878
#define GZ_BLOCKS (GEMM_BLOCKS + CZBLOCKS)

#define KGC8_BLOCKS ((EKG / 8 + 255) / 256)     // 977
#define CUI4_BLOCKS ((EUI_HALF / 4 + 255) / 256) // 977
#define SF2_QBLOCKS ((2 * NB + 255) / 256)      // 32
#define SF2_BLOCKS (2 * CUI4_BLOCKS + SF2_QBLOCKS)

#define EA_KG_BLOCKS 2048
#define EA_UI_BLOCKS 256
#define EB_BLOCKS 512

#define DEGZ_F4 (MAXLE / 4)                     // 25,000
#define SF1_THREADS (3 * NB + DEGZ_F4)          // 37,288
#define SF1_BLOCKS ((SF1_THREADS + 255) / 256)

#define QK_BLOCKS 512                           // NB*32/256

// ---------------- scratch (static device globals; no allocation) ----------------
__device__ float g_y[NE * DIM];             // entity_emb @ W^T
__device__ float g_aggC[MAXLE * DIM];       // KG segment sum (dense live-entity rows)
__device__ float g_degC[MAXLE];             // KG in-degree (dense; zeroed each call)
__device__ float g_itemkg[NI * DIM];        // per-item post-processed KG embedding
__device__ float g_agg2C[MAXLN * DIM];      // UI segment sum (dense live-node rows)
__device__ float g_gate[NREL * DIM];        // sigmoid(relation_emb)
__device__ int g_remapE[NE];                // 0=unclaimed, >=2 -> dense id+2 (PERSISTENT,
__device__ int g_remapN[NNODES];            //   input-deterministic, idempotent claims)
__device__ int g_nLiveE, g_nLiveN;
__device__ int g_nKG, g_nUIA, g_nUIB;       // compaction counters (reset in SF1 t==0)
__device__ int   g_ksr[EKG];                // src | rel<<18
__device__ int   g_kdst[EKG];               // remapped dense dst
__device__ int   g_apk[EUI_HALF];           // rr | cc<<14 (A: row=item live id, col=user)
__device__ float g_aval[EUI_HALF];
__device__ int   g_bpk[EUI_HALF];           // rr | cc<<14 (B: row=user live id, col=item node)
__device__ float g_bval[EUI_HALF];

// vectorized no-return global atomic add (sm_90+)
__device__ __forceinline__ void red_add_v4(float* addr, float x, float y, float z, float w) {
    asm volatile("red.global.add.v4.f32 [%0], {%1,%2,%3,%4};"
                 :: "l"(addr), "f"(x), "f"(y), "f"(z), "f"(w)
                 : "memory");
}

__device__ __forceinline__ unsigned long long pack2(float a, float b) {
    unsigned long long r;
    asm("mov.b64 %0, {%1, %2};" : "=l"(r) : "f"(a), "f"(b));
    return r;
}
__device__ __forceinline__ void unpack2(unsigned long long v, float& a, float& b) {
    asm("mov.b64 {%0, %1}, %2;" : "=f"(a), "=f"(b) : "l"(v));
}
__device__ __forceinline__ void fma2(unsigned long long& d, unsigned long long a,
                                     unsigned long long b) {
    asm("fma.rn.f32x2 %0, %1, %2, %3;" : "=l"(d) : "l"(a), "l"(b), "l"(d));
}

__device__ __forceinline__ void claimE(int ent) {
    if (atomicCAS(&g_remapE[ent], 0, 1) == 0)
        g_remapE[ent] = 2 + atomicAdd(&g_nLiveE, 1);
}

// warp-scan compaction helper: cnt in [0,8]; returns write base for this thread
__device__ __forceinline__ int warp_scan_base(int cnt, int lane, int* counter) {
    int inc = cnt;
#pragma unroll
    for (int o = 1; o < 32; o <<= 1) {
        int v = __shfl_up_sync(0xffffffffu, inc, o);
        if (lane >= o) inc += v;
    }
    int total = __shfl_sync(0xffffffffu, inc, 31);
    int base = 0;
    if (lane == 0 && total) base = atomicAdd(counter, total);
    base = __shfl_sync(0xffffffffu, base, 0);
    return base + inc - cnt;
}

// ---------------- SIDE STREAM: GEMM + gate + zero scratch (no deps) ----------------
__global__ void gemm_zero_kernel(const float* __restrict__ x, const float* __restrict__ W,
                                 const float* __restrict__ rel_emb) {
    int b = blockIdx.x;
    int tid = threadIdx.x;  // 256
    if (b < GEMM_BLOCKS) {
        __shared__ float sWt[DIM][DIM];   // sWt[k][o] = W[o][k]
        for (int idx = tid; idx < DIM * DIM; idx += 256) {
            int o = idx >> 6, k = idx & 63;
            sWt[k][o] = W[idx];
        }
        __syncthreads();
        int row = b * 256 + tid;
        if (row >= NE) return;
        const float4* xp = reinterpret_cast<const float4*>(x + (size_t)row * DIM);
        unsigned long long acc[32];
#pragma unroll
        for (int m = 0; m < 32; m++) acc[m] = 0ull;
#pragma unroll 4
        for (int kc = 0; kc < 16; kc++) {
            float4 xq = __ldg(xp + kc);
#pragma unroll
            for (int j = 0; j < 4; j++) {
                float xv = (j == 0) ? xq.x : (j == 1) ? xq.y : (j == 2) ? xq.z : xq.w;
                unsigned long long xx = pack2(xv, xv);
                const float4* wrow = reinterpret_cast<const float4*>(sWt[kc * 4 + j]);
#pragma unroll
                for (int o4 = 0; o4 < 16; o4++) {
                    float4 w = wrow[o4];
                    fma2(acc[2 * o4],     xx, pack2(w.x, w.y));
                    fma2(acc[2 * o4 + 1], xx, pack2(w.z, w.w));
                }
            }
        }
        float4* yp = reinterpret_cast<float4*>(g_y + (size_t)row * DIM);
#pragma unroll
        for (int j = 0; j < 16; j++) {
            float a0, a1, b0, b1;
            unpack2(acc[2 * j], a0, a1);
            unpack2(acc[2 * j + 1], b0, b1);
            yp[j] = make_float4(a0, a1, b0, b1);
        }
        return;
    }
    b -= GEMM_BLOCKS;
    {
        if (b == 0) {
            for (int i = tid; i < NREL * DIM; i += 256) {
                float v = rel_emb[i];
                g_gate[i] = 1.0f / (1.0f + __expf(-v));
            }
        }
        float4 z = make_float4(0.f, 0.f, 0.f, 0.f);
        int base = b * 2048 + tid;
#pragma unroll
        for (int j = 0; j < 8; j++) {
            int i = base + j * 256;
            if (i < ZF4_AGGC) {
                reinterpret_cast<float4*>(g_aggC)[i] = z;     // full extent (no g_nLiveE dep)
            } else if (i < ZF4_TOTC) {
                reinterpret_cast<float4*>(g_agg2C)[i - ZF4_AGGC] = z;
            }
        }
    }
}

// ---------------- K1 (SF1): batch-node tickets + zero degC + reset counters ----------------
__global__ void sf1_kernel(const int* __restrict__ qu,
                           const int* __restrict__ qi,
                           const int* __restrict__ qn) {
    int t = blockIdx.x * blockDim.x + threadIdx.x;
    if (t == 0) { g_nKG = 0; g_nUIA = 0; g_nUIB = 0; }
    if (t < 3 * NB) {
        int node;
        if (t < NB) node = __ldg(qu + t);
        else if (t < 2 * NB) node = NU + __ldg(qi + t - NB);
        else node = NU + __ldg(qn + t - 2 * NB);
        if (atomicCAS(&g_remapN[node], 0, 1) == 0)
            g_remapN[node] = 2 + atomicAdd(&g_nLiveN, 1);
    } else {
        int z = t - 3 * NB;
        if (z < DEGZ_F4)
            reinterpret_cast<float4*>(g_degC)[z] = make_float4(0.f, 0.f, 0.f, 0.f);
    }
}

// ---------------- K2 (SF2): fused entity claims + UI compaction, 4 edges/thread ----------------
__global__ void sf2_kernel(const int* __restrict__ urow, const int* __restrict__ ucol,
                           const float* __restrict__ uval,
                           const int* __restrict__ i2e,
                           const int* __restrict__ qi, const int* __restrict__ qn) {
    int b = blockIdx.x;
    int tid = threadIdx.x;
    int lane = tid & 31;
    if (b < 2 * CUI4_BLOCKS) {
        int half = (b < CUI4_BLOCKS) ? 0 : 1;
        int bb = (half == 0) ? b : b - CUI4_BLOCKS;
        int t = bb * 256 + tid;          // group index within half
        int cnt = 0;
        int pk[4];
        float vv[4];
        if (t < EUI_HALF / 4) {
            int g = half * (EUI_HALF / 4) + t;  // global int4 index
            int4 r4 = __ldg(reinterpret_cast<const int4*>(urow) + g);
            int4 c4 = __ldg(reinterpret_cast<const int4*>(ucol) + g);
            float4 v4 = __ldg(reinterpret_cast<const float4*>(uval) + g);
            int rows[4] = {r4.x, r4.y, r4.z, r4.w};
            int cols[4] = {c4.x, c4.y, c4.z, c4.w};
            float vals[4] = {v4.x, v4.y, v4.z, v4.w};
            int m0 = g_remapN[rows[0]];
            int m1 = g_remapN[rows[1]];
            int m2 = g_remapN[rows[2]];
            int m3 = g_remapN[rows[3]];
            int ms[4] = {m0, m1, m2, m3};
#pragma unroll
            for (int i = 0; i < 4; i++) {
                if (ms[i] >= 2) {
                    pk[cnt] = (ms[i] - 2) | (cols[i] << 14);
                    vv[cnt] = vals[i];
                    cnt++;
                    if (half == 0) claimE(__ldg(i2e + (cols[i] - NU)));
                }
            }
        }
        int off = warp_scan_base(cnt, lane, half ? &g_nUIA : &g_nUIB);
        if (half) {
            for (int i = 0; i < cnt; i++) { g_apk[off + i] = pk[i]; g_aval[off + i] = vv[i]; }
        } else {
            for (int i = 0; i < cnt; i++) { g_bpk[off + i] = pk[i]; g_bval[off + i] = vv[i]; }
        }
    } else {
        int r = (b - 2 * CUI4_BLOCKS) * 256 + tid;
        if (r < NB) claimE(__ldg(i2e + __ldg(qi + r)));
        else if (r < 2 * NB) claimE(__ldg(i2e + __ldg(qn + r - NB)));
    }
}

// ---------------- K3: KG edge compaction + deg, 8 edges/thread ----------------
__global__ void kg_compact_kernel(const int* __restrict__ ksrc, const int* __restrict__ kdst,
                                  const int* __restrict__ krel) {
    int tid = threadIdx.x;
    int lane = tid & 31;
    int t = blockIdx.x * 256 + tid;      // 8-edge group index
    int cnt = 0;
    int srO[8], drO[8];
    if (t < EKG / 8) {
        int4 d4a = __ldg(reinterpret_cast<const int4*>(kdst) + 2 * t);
        int4 d4b = __ldg(reinterpret_cast<const int4*>(kdst) + 2 * t + 1);
        int ds[8] = {d4a.x, d4a.y, d4a.z, d4a.w, d4b.x, d4b.y, d4b.z, d4b.w};
        int ms[8];
#pragma unroll
        for (int i = 0; i < 8; i++) ms[i] = g_remapE[ds[i]];
        bool any = false;
#pragma unroll
        for (int i = 0; i < 8; i++) any |= (ms[i] >= 2);
        if (any) {
            int4 s4a = __ldg(reinterpret_cast<const int4*>(ksrc) + 2 * t);
            int4 s4b = __ldg(reinterpret_cast<const int4*>(ksrc) + 2 * t + 1);
            int4 r4a = __ldg(reinterpret_cast<const int4*>(krel) + 2 * t);
            int4 r4b = __ldg(reinterpret_cast<const int4*>(krel) + 2 * t + 1);
            int ss[8] = {s4a.x, s4a.y, s4a.z, s4a.w, s4b.x, s4b.y, s4b.z, s4b.w};
            int rs[8] = {r4a.x, r4a.y, r4a.z, r4a.w, r4b.x, r4b.y, r4b.z, r4b.w};
#pragma unroll
            for (int i = 0; i < 8; i++) {
                if (ms[i] >= 2) {
                    int dr = ms[i] - 2;
                    srO[cnt] = ss[i] | (rs[i] << 18);
                    drO[cnt] = dr;
                    cnt++;
                    atomicAdd(&g_degC[dr], 1.0f);
                }
            }
        }
    }
    int off = warp_scan_base(cnt, lane, &g_nKG);
    for (int i = 0; i < cnt; i++) { g_ksr[off + i] = srO[i]; g_kdst[off + i] = drO[i]; }
}

// ---------------- K4: compacted KG edges (8 thr/edge) + UI user-gather edges (8 thr/edge) ----------------
__global__ void edgeA_kernel(const float* __restrict__ user_emb) {
    int b = blockIdx.x;
    int tid = threadIdx.x;
    int q = tid & 7;
    if (b < EA_KG_BLOCKS) {
        int n = g_nKG;
        int slot = (b * 256 + tid) >> 3;
        for (; slot < n; slot += (EA_KG_BLOCKS * 256) / 8) {
            int sr = g_ksr[slot], dr = g_kdst[slot];
            int s = sr & 0x3FFFF, r = (int)((unsigned)sr >> 18);
            const float4* yp = reinterpret_cast<const float4*>(g_y + (size_t)s * DIM) + q;
            const float4* gp = reinterpret_cast<const float4*>(g_gate + r * DIM) + q;
            float4 v0 = __ldg(yp);
            float4 v1 = __ldg(yp + 8);
            float4 g0 = __ldg(gp);
            float4 g1 = __ldg(gp + 8);
            float* ap = g_aggC + (size_t)dr * DIM + q * 4;
            red_add_v4(ap,      v0.x * g0.x, v0.y * g0.y, v0.z * g0.z, v0.w * g0.w);
            red_add_v4(ap + 32, v1.x * g1.x, v1.y * g1.y, v1.z * g1.z, v1.w * g1.w);
        }
    } else {
        int n = g_nUIA;
        int slot = ((b - EA_KG_BLOCKS) * 256 + tid) >> 3;
        for (; slot < n; slot += (EA_UI_BLOCKS * 256) / 8) {
            int pk = g_apk[slot];
            int rr = pk & 0x3FFF, cc = (int)((unsigned)pk >> 14);
            float w = g_aval[slot];
            const float4* sp = reinterpret_cast<const float4*>(user_emb + (size_t)cc * DIM) + q;
            float4 v0 = __ldg(sp);
            float4 v1 = __ldg(sp + 8);
            float* ap = g_agg2C + (size_t)rr * DIM + q * 4;
            red_add_v4(ap,      w * v0.x, w * v0.y, w * v0.z, w * v0.w);
            red_add_v4(ap + 32, w * v1.x, w * v1.y, w * v1.z, w * v1.w);
        }
    }
}

// ---------------- K5: per-ITEM post (16 lanes/row, float4), live-entity only ----------------
__global__ void item_post_kernel(const float* __restrict__ ent, const int* __restrict__ i2e) {
    int tid = threadIdx.x;
    int lane = tid & 31;
    int half = lane >> 4;
    int l16 = lane & 15;
    int item = blockIdx.x * 16 + (tid >> 5) * 2 + half;
    if (item >= NI) return;
    int e = __ldg(i2e + item);
    int m = g_remapE[e];
    if (m < 2) return;                 // item not visible to this batch; itemkg never read
    int re = m - 2;
    float inv = 1.0f / fmaxf(g_degC[re], 1.0f);
    float4 a = *reinterpret_cast<const float4*>(&g_aggC[(size_t)re * DIM + l16 * 4]);
    float4 x0 = __ldg(reinterpret_cast<const float4*>(&ent[(size_t)e * DIM + l16 * 4]));
    float vx = fmaf(a.x, inv, x0.x);
    float vy = fmaf(a.y, inv, x0.y);
    float vz = fmaf(a.z, inv, x0.z);
    float vw = fmaf(a.w, inv, x0.w);
    vx = (vx > 0.f) ? vx : (__expf(vx) - 1.f);
    vy = (vy > 0.f) ? vy : (__expf(vy) - 1.f);
    vz = (vz > 0.f) ? vz : (__expf(vz) - 1.f);
    vw = (vw > 0.f) ? vw : (__expf(vw) - 1.f);
    float ss = vx * vx + vy * vy + vz * vz + vw * vw;
#pragma unroll
    for (int o = 8; o; o >>= 1) ss += __shfl_xor_sync(0xffffffffu, ss, o);
    float scale = 1.0f / fmaxf(sqrtf(ss), 1e-12f);
    float4 out = make_float4(vx * scale, vy * scale, vz * scale, vw * scale);
    *reinterpret_cast<float4*>(&g_itemkg[(size_t)item * DIM + l16 * 4]) = out;
}

// ---------------- K6: compacted UI item-gather edges (8 thr/edge) ----------------
__global__ void edgeB_kernel() {
    int tid = threadIdx.x;
    int q = tid & 7;
    int n = g_nUIB;
    int slot = (blockIdx.x * 256 + tid) >> 3;
    for (; slot < n; slot += (EB_BLOCKS * 256) / 8) {
        int pk = g_bpk[slot];
        int rr = pk & 0x3FFF, cc = (int)((unsigned)pk >> 14);
        float w = g_bval[slot];
        const float4* sp = reinterpret_cast<const float4*>(g_itemkg + (size_t)(cc - NU) * DIM) + q;
        float4 v0 = __ldg(sp);
        float4 v1 = __ldg(sp + 8);
        float* ap = g_agg2C + (size_t)rr * DIM + q * 4;
        red_add_v4(ap,      w * v0.x, w * v0.y, w * v0.z, w * v0.w);
        red_add_v4(ap + 32, w * v1.x, w * v1.y, w * v1.z, w * v1.w);
    }
}

// ---------------- K7: fused intent + queries ----------------
__global__ void query_kernel(const int* __restrict__ qu, const int* __restrict__ qi,
                             const int* __restrict__ qn,
                             const float* __restrict__ user_emb,
                             const float* __restrict__ router_w,
                             const float* __restrict__ router_b,
                             const float* __restrict__ iw,
                             const float* __restrict__ rel_emb,
                             float* __restrict__ out) {
    __shared__ float s_intent[2 * DIM];
    __shared__ float s_sw[2][NREL];
    int tid = threadIdx.x;  // 256
    if (tid < 2) {
        float m = -1e30f;
#pragma unroll
        for (int k = 0; k < NREL; k++) m = fmaxf(m, __ldg(iw + tid * NREL + k));
        float s = 0.f;
#pragma unroll
        for (int k = 0; k < NREL; k++) {
            float e = __expf(__ldg(iw + tid * NREL + k) - m);
            s_sw[tid][k] = e; s += e;
        }
        float inv = 1.0f / s;
#pragma unroll
        for (int k = 0; k < NREL; k++) s_sw[tid][k] *= inv;
    }
    __syncthreads();
    if (tid < 64) {
#pragma unroll
        for (int intent = 0; intent < 2; intent++) {
            float acc = 0.f;
#pragma unroll
            for (int k = 0; k < NREL; k++) acc += s_sw[intent][k] * __ldg(rel_emb + k * DIM + tid);
            s_intent[intent * DIM + tid] = acc;
        }
    }
    __syncthreads();

    int warp = (blockIdx.x * blockDim.x + tid) >> 5;
    int lane = tid & 31;
    if (warp >= NB) return;
    int uu = __ldg(qu + warp), pi = __ldg(qi + warp), ni = __ldg(qn + warp);
    int ru = g_remapN[uu] - 2;
    int rp = g_remapN[NU + pi] - 2;
    int rn = g_remapN[NU + ni] - 2;

    float2 ue0 = __ldg(reinterpret_cast<const float2*>(&user_emb[(size_t)uu * DIM + lane * 2]));
    float2 ag = *reinterpret_cast<const float2*>(&g_agg2C[(size_t)ru * DIM + lane * 2]);
    float fux = 0.5f * (ue0.x + ag.x);
    float fuy = 0.5f * (ue0.y + ag.y);

    float2 rw0 = __ldg(reinterpret_cast<const float2*>(&router_w[lane * 2]));
    float2 rw1 = __ldg(reinterpret_cast<const float2*>(&router_w[DIM + lane * 2]));
    float l0 = fux * rw0.x + fuy * rw0.y;
    float l1 = fux * rw1.x + fuy * rw1.y;
#pragma unroll
    for (int o = 16; o; o >>= 1) {
        l0 += __shfl_xor_sync(0xffffffffu, l0, o);
        l1 += __shfl_xor_sync(0xffffffffu, l1, o);
    }
    l0 += __ldg(router_b + 0);
    l1 += __ldg(router_b + 1);
    float m = fmaxf(l0, l1);
    float e0 = __expf(l0 - m), e1 = __expf(l1 - m);
    float inv = 1.0f / (e0 + e1);
    float p0 = e0 * inv, p1 = e1 * inv;

    float2 i0 = *reinterpret_cast<const float2*>(&s_intent[lane * 2]);
    float2 i1 = *reinterpret_cast<const float2*>(&s_intent[DIM + lane * 2]);
    float uex = fux + p0 * i0.x + p1 * i1.x;
    float uey = fuy + p0 * i0.y + p1 * i1.y;

    float2 ik = *reinterpret_cast<const float2*>(&g_itemkg[(size_t)pi * DIM + lane * 2]);
    float2 a2 = *reinterpret_cast<const float2*>(&g_agg2C[(size_t)rp * DIM + lane * 2]);
    float pos = uex * (1.5f * ik.x + 0.5f * a2.x) + uey * (1.5f * ik.y + 0.5f * a2.y);

    float2 nk = *reinterpret_cast<const float2*>(&g_itemkg[(size_t)ni * DIM + lane * 2]);
    float2 n2 = *reinterpret_cast<const float2*>(&g_agg2C[(size_t)rn * DIM + lane * 2]);
    float neg = uex * (1.5f * nk.x + 0.5f * n2.x) + uey * (1.5f * nk.y + 0.5f * n2.y);

#pragma unroll
    for (int o = 16; o; o >>= 1) {
        pos += __shfl_xor_sync(0xffffffffu, pos, o);
        neg += __shfl_xor_sync(0xffffffffu, neg, o);
    }
    if (lane == 0) {
        out[warp] = pos;
        out[NB + warp] = neg;
    }
}

// ---------------- launch (fork/join: GEMM+zero overlaps SF1/SF2/KG-compact) ----------------
extern "C" void kernel_launch(void* const* d_in, const int* in_sizes, int n_in,
                              void* d_out, int out_size) {
    const int*   u          = (const int*)d_in[0];
    const int*   it         = (const int*)d_in[1];
    const int*   neg_i      = (const int*)d_in[2];
    const float* user_emb   = (const float*)d_in[3];
    const float* entity_emb = (const float*)d_in[4];
    const float* rel_emb    = (const float*)d_in[5];
    const float* intent_w   = (const float*)d_in[6];
    const float* router_w   = (const float*)d_in[7];
    const float* router_b   = (const float*)d_in[8];
    const float* kg_w       = (const float*)d_in[9];
    const float* ui_vals    = (const float*)d_in[10];
    const int*   item2ent   = (const int*)d_in[11];
    const int*   kg_src     = (const int*)d_in[12];
    const int*   kg_dst     = (const int*)d_in[13];
    const int*   kg_rel     = (const int*)d_in[14];
    const int*   ui_row     = (const int*)d_in[15];
    const int*   ui_col     = (const int*)d_in[16];
    float* out = (float*)d_out;

    // lazily-created host-side stream/events (no device memory; identical GPU work per call)
    static cudaStream_t s1 = nullptr;
    static cudaEvent_t evFork = nullptr, evJoin = nullptr;
    if (s1 == nullptr) {
        cudaStreamCreateWithFlags(&s1, cudaStreamNonBlocking);
        cudaEventCreateWithFlags(&evFork, cudaEventDisableTiming);
        cudaEventCreateWithFlags(&evJoin, cudaEventDisableTiming);
    }

    // fork: side stream runs GEMM + gate + scratch zeroing (no dependencies)
    cudaEventRecord(evFork, 0);
    cudaStreamWaitEvent(s1, evFork, 0);
    gemm_zero_kernel<<<GZ_BLOCKS, 256, 0, s1>>>(entity_emb, kg_w, rel_emb);
    cudaEventRecord(evJoin, s1);

    // main chain: liveness + compaction
    sf1_kernel<<<SF1_BLOCKS, 256>>>(u, it, neg_i);
    sf2_kernel<<<SF2_BLOCKS, 256>>>(ui_row, ui_col, ui_vals, item2ent, it, neg_i);
    kg_compact_kernel<<<KGC8_BLOCKS, 256>>>(kg_src, kg_dst, kg_rel);

    // join: edgeA needs g_y/gate/zeros from side stream
    cudaStreamWaitEvent(0, evJoin, 0);
    edgeA_kernel<<<EA_KG_BLOCKS + EA_UI_BLOCKS, 256>>>(user_emb);
    item_post_kernel<<<(NI + 15) / 16, 256>>>(entity_emb, item2ent);
    edgeB_kernel<<<EB_BLOCKS, 256>>>();
    query_kernel<<<QK_BLOCKS, 256>>>(u, it, neg_i, user_emb, router_w, router_b,
                                     intent_w, rel_emb, out);
}